// round 3
// baseline (speedup 1.0000x reference)
#include <cuda_runtime.h>
#include <math.h>

#define BB 4
#define NA 50
#define SZ 256
#define SS (SZ*SZ)
#define NC 32
#define PP 512
#define CEN 127.5f

// ---------------- scratch (static device allocations) ----------------
__device__ float g_h[PP];                // ramp filter impulse response
__device__ float g_imgm[BB*SS];          // masked y_img_prev
__device__ float g_diff[BB*NA*SZ];       // Ay - x
__device__ float g_filt[BB*NA*SZ];       // filtered sinogram (scaled)
__device__ float g_h1[BB*NC*SS];         // conv1 output
__device__ float g_h2[BB*NC*SS];         // conv2 output
__device__ float g_up[BB*SS];            // fallback y_img_update buffer

// ---------------- 1. ramp filter h = irfft(2*rfftfreq(512)) ----------------
__global__ void k_hfilt() {
    int n = threadIdx.x;  // 0..511
    double acc = (n & 1) ? -1.0 : 1.0;   // k = P/2 term: coeff 1 * cos(pi n)
    for (int k = 1; k < 256; ++k) {
        acc += (4.0 * k / 512.0) * cos(2.0 * M_PI * (double)k * (double)n / 512.0);
    }
    g_h[n] = (float)(acc / 512.0);
}

// ---------------- 2. mask input image ----------------
__global__ void k_maskimg(const float* __restrict__ yprev) {
    int idx = blockIdx.x * 256 + threadIdx.x;   // B*SS threads
    int p = idx & (SS - 1);
    int i = p >> 8, j = p & 255;
    float dy = (float)i - CEN, dx = (float)j - CEN;
    float m = (dy*dy + dx*dx <= 16384.0f) ? 1.0f : 0.0f;
    g_imgm[idx] = yprev[idx] * m;
}

// ---------------- bilinear sample, mode='constant' cval=0 ----------------
__device__ __forceinline__ float bilin256(const float* __restrict__ im, float r, float c) {
    float rf = floorf(r), cf = floorf(c);
    int r0 = (int)rf, c0 = (int)cf;
    float wr = r - rf, wc = c - cf;
    float v = 0.0f;
    bool r0v = (r0 >= 0) && (r0 <= 255);
    bool r1v = (r0 >= -1) && (r0 <= 254);
    bool c0v = (c0 >= 0) && (c0 <= 255);
    bool c1v = (c0 >= -1) && (c0 <= 254);
    if (r0v) {
        const float* row = im + r0 * SZ;
        if (c0v) v += row[c0]     * (1.0f - wr) * (1.0f - wc);
        if (c1v) v += row[c0 + 1] * (1.0f - wr) * wc;
    }
    if (r1v) {
        const float* row = im + (r0 + 1) * SZ;
        if (c0v) v += row[c0]     * wr * (1.0f - wc);
        if (c1v) v += row[c0 + 1] * wr * wc;
    }
    return v;
}

// ---------------- 3. radon forward + subtract x_sinogram ----------------
__global__ void k_radon(const float* __restrict__ x_sino,
                        const float* __restrict__ angles) {
    __shared__ float s_red[512];
    int a = blockIdx.x, b = blockIdx.y;
    int tid = threadIdx.x;
    int s = tid & 255, half = tid >> 8;
    float ca = cosf(angles[a]), sa = sinf(angles[a]);
    float sf = (float)s - CEN;
    const float* im = &g_imgm[b * SS];
    float sum = 0.0f;
    int t0 = half * 128;
    #pragma unroll 4
    for (int t = t0; t < t0 + 128; ++t) {
        float tf = (float)t - CEN;
        float row = sf * sa + tf * ca + CEN;   // y + c
        float col = sf * ca - tf * sa + CEN;   // x + c
        sum += bilin256(im, row, col);
    }
    s_red[tid] = sum;
    __syncthreads();
    if (half == 0) {
        float tot = s_red[s] + s_red[s + 256];
        int o = (b * NA + a) * SZ + s;
        g_diff[o] = tot - x_sino[o];
    }
}

// ---------------- 4. ramp filter via circular convolution ----------------
__global__ void k_filter() {
    __shared__ float sd[SZ];
    __shared__ float sh[PP];
    int a = blockIdx.x, b = blockIdx.y;
    int n = threadIdx.x;
    int base = (b * NA + a) * SZ;
    sd[n] = g_diff[base + n];
    sh[n] = g_h[n];
    sh[n + 256] = g_h[n + 256];
    __syncthreads();
    float acc = 0.0f;
    #pragma unroll 8
    for (int m = 0; m < SZ; ++m) {
        acc += sd[m] * sh[(n - m + PP) & (PP - 1)];
    }
    g_filt[base + n] = acc * (float)(M_PI / (2.0 * NA));
}

// ---------------- 5. backprojection + update ----------------
__global__ void k_backproj(const float* __restrict__ yprev,
                           const float* __restrict__ angles,
                           const float* __restrict__ step,
                           float* __restrict__ out_up) {
    __shared__ float s_sino[25 * SZ];
    __shared__ float s_cos[NA], s_sin[NA];
    int i = blockIdx.x, b = blockIdx.y;
    int j = threadIdx.x;
    if (j < NA) { s_cos[j] = cosf(angles[j]); s_sin[j] = sinf(angles[j]); }
    __syncthreads();
    float xx = (float)j - CEN, yy = (float)i - CEN;
    float acc = 0.0f;
    for (int ch = 0; ch < 2; ++ch) {
        for (int al = 0; al < 25; ++al) {
            s_sino[al * SZ + j] = g_filt[(b * NA + ch * 25 + al) * SZ + j];
        }
        __syncthreads();
        #pragma unroll 5
        for (int al = 0; al < 25; ++al) {
            int a = ch * 25 + al;
            float det = xx * s_cos[a] + yy * s_sin[a] + CEN;
            float df = floorf(det);
            int i0 = (int)df;
            i0 = i0 < 0 ? 0 : (i0 > SZ - 2 ? SZ - 2 : i0);
            float w = det - (float)i0;
            float v = s_sino[al * SZ + i0] * (1.0f - w) + s_sino[al * SZ + i0 + 1] * w;
            if (det >= 0.0f && det <= (float)(SZ - 1)) acc += v;
        }
        __syncthreads();
    }
    float m = (xx*xx + yy*yy <= 16384.0f) ? 1.0f : 0.0f;
    int o = b * SS + i * SZ + j;
    out_up[o] = yprev[o] + step[0] * (acc * m);
}

// ---------------- 6. conv1: 2 -> 32, 3x3 SAME, ReLU ----------------
__global__ void k_conv1(const float* __restrict__ yup,
                        const float* __restrict__ ycat,
                        const float* __restrict__ w1,
                        const float* __restrict__ b1) {
    __shared__ float s_w[NC * 2 * 9];
    __shared__ float s_b[NC];
    int tid = threadIdx.x;
    // FIX: 576 weights, 256 threads -> strided cooperative load
    for (int k = tid; k < NC * 18; k += 256) s_w[k] = w1[k];
    if (tid < NC) s_b[tid] = b1[tid];
    __syncthreads();
    int idx = blockIdx.x * 256 + tid;
    int b = idx >> 16;
    int p = idx & (SS - 1);
    int i = p >> 8, j = p & 255;
    float iv0[9], iv1[9];
    #pragma unroll
    for (int ky = 0; ky < 3; ++ky) {
        #pragma unroll
        for (int kx = 0; kx < 3; ++kx) {
            int y = i + ky - 1, x = j + kx - 1;
            bool ok = (y >= 0) && (y < SZ) && (x >= 0) && (x < SZ);
            int gi = b * SS + y * SZ + x;
            iv0[ky*3+kx] = ok ? yup[gi]  : 0.0f;
            iv1[ky*3+kx] = ok ? ycat[gi] : 0.0f;
        }
    }
    for (int oc = 0; oc < NC; ++oc) {
        float acc = s_b[oc];
        const float* w = &s_w[oc * 18];
        #pragma unroll
        for (int k = 0; k < 9; ++k) acc += iv0[k] * w[k];
        #pragma unroll
        for (int k = 0; k < 9; ++k) acc += iv1[k] * w[9 + k];
        g_h1[((b * NC + oc) << 16) + p] = fmaxf(acc, 0.0f);
    }
}

// ---------------- 7. conv2: 32 -> 32, 3x3 SAME, ReLU ----------------
#define ICH 16
__global__ void __launch_bounds__(256) k_conv2(const float* __restrict__ w2,
                                               const float* __restrict__ b2) {
    __shared__ __align__(16) float s_w[ICH * 9 * 32];   // [ic][k][oc]
    __shared__ float s_in[ICH * 10 * 34];               // [ic][row][col]
    __shared__ float s_b[NC];
    int tid = threadIdx.x;
    int q = tid & 7, r = (tid >> 3) & 7, og = tid >> 6;
    int b = blockIdx.z;
    int gx0 = blockIdx.x * 32 - 1;
    int gy0 = blockIdx.y * 8 - 1;
    if (tid < NC) s_b[tid] = b2[tid];

    float acc[8][4];
    #pragma unroll
    for (int o = 0; o < 8; ++o)
        #pragma unroll
        for (int p = 0; p < 4; ++p) acc[o][p] = 0.0f;

    for (int cc = 0; cc < 2; ++cc) {
        int icb = cc * ICH;
        __syncthreads();
        for (int idx = tid; idx < ICH * 288; idx += 256) {
            int ic = idx / 288, rem = idx % 288;
            int k = rem >> 5, oc = rem & 31;
            s_w[idx] = w2[oc * 288 + (icb + ic) * 9 + k];
        }
        for (int idx = tid; idx < ICH * 340; idx += 256) {
            int ic = idx / 340, rem = idx % 340;
            int rr = rem / 34, ccx = rem % 34;
            int gy = gy0 + rr, gx = gx0 + ccx;
            bool ok = (gy >= 0) && (gy < SZ) && (gx >= 0) && (gx < SZ);
            s_in[idx] = ok ? g_h1[((b * NC + icb + ic) << 16) + gy * SZ + gx] : 0.0f;
        }
        __syncthreads();

        for (int ic = 0; ic < ICH; ++ic) {
            const float* inb = &s_in[ic * 340];
            const float* wb  = &s_w[ic * 288];
            #pragma unroll
            for (int ky = 0; ky < 3; ++ky) {
                float iv[6];
                const float* rowp = inb + (r + ky) * 34 + q * 4;
                #pragma unroll
                for (int m = 0; m < 6; ++m) iv[m] = rowp[m];
                #pragma unroll
                for (int kx = 0; kx < 3; ++kx) {
                    const float4 wa = *(const float4*)&wb[(ky * 3 + kx) * 32 + og * 8];
                    const float4 wbv = *(const float4*)&wb[(ky * 3 + kx) * 32 + og * 8 + 4];
                    float wv[8] = {wa.x, wa.y, wa.z, wa.w, wbv.x, wbv.y, wbv.z, wbv.w};
                    #pragma unroll
                    for (int o = 0; o < 8; ++o)
                        #pragma unroll
                        for (int p = 0; p < 4; ++p)
                            acc[o][p] += wv[o] * iv[kx + p];
                }
            }
        }
    }
    int gy = blockIdx.y * 8 + r;
    int gxb = blockIdx.x * 32 + q * 4;
    #pragma unroll
    for (int o = 0; o < 8; ++o) {
        int oc = og * 8 + o;
        float bias = s_b[oc];
        int base = ((b * NC + oc) << 16) + gy * SZ + gxb;
        #pragma unroll
        for (int p = 0; p < 4; ++p)
            g_h2[base + p] = fmaxf(acc[o][p] + bias, 0.0f);
    }
}

// ---------------- 8. conv3: 32 -> 1, 3x3 SAME ----------------
__global__ void k_conv3(const float* __restrict__ w3,
                        const float* __restrict__ b3,
                        float* __restrict__ out_img) {
    __shared__ float s_w[NC * 9];
    int tid = threadIdx.x;
    // FIX: 288 weights, 256 threads -> strided cooperative load
    for (int k = tid; k < NC * 9; k += 256) s_w[k] = w3[k];
    __syncthreads();
    int idx = blockIdx.x * 256 + tid;
    int b = idx >> 16;
    int p = idx & (SS - 1);
    int i = p >> 8, j = p & 255;
    float acc = b3[0];
    for (int ic = 0; ic < NC; ++ic) {
        const float* in = &g_h2[(b * NC + ic) << 16];
        const float* w = &s_w[ic * 9];
        #pragma unroll
        for (int ky = 0; ky < 3; ++ky) {
            int y = i + ky - 1;
            if (y < 0 || y >= SZ) continue;
            #pragma unroll
            for (int kx = 0; kx < 3; ++kx) {
                int x = j + kx - 1;
                if (x < 0 || x >= SZ) continue;
                acc += in[y * SZ + x] * w[ky * 3 + kx];
            }
        }
    }
    out_img[idx] = acc;
}

// ---------------- launch: input-order-robust dispatch ----------------
extern "C" void kernel_launch(void* const* d_in, const int* in_sizes, int n_in,
                              void* d_out, int out_size) {
    // Identify inputs by element-count fingerprint. Two plausible orderings:
    //   dict order : x_sino, y_prev, y_cat, angles, step, w1, b1, w2, b2, w3, b3
    //   alpha order: angles, b1, b2, b3, step, w1, w2, w3, x_sino, y_cat, y_prev
    const float *x_sino = 0, *y_prev = 0, *y_cat = 0, *angles = 0, *step = 0;
    const float *w1 = 0, *b1 = 0, *w2 = 0, *b2 = 0, *w3 = 0, *b3 = 0;

    int ix = -1;
    for (int i = 0; i < n_in; ++i) if (in_sizes[i] == 51200) ix = i;
    bool dict_order = (ix == 0);

    int n262 = 0, n32 = 0, n1 = 0;
    for (int i = 0; i < n_in; ++i) {
        const float* p = (const float*)d_in[i];
        switch (in_sizes[i]) {
            case 51200: x_sino = p; break;
            case 50:    angles = p; break;
            case 576:   w1 = p; break;
            case 9216:  w2 = p; break;
            case 288:   w3 = p; break;
            case 262144:
                if (dict_order) { if (n262 == 0) y_prev = p; else y_cat = p; }
                else            { if (n262 == 0) y_cat  = p; else y_prev = p; }
                ++n262; break;
            case 32:
                if (n32 == 0) b1 = p; else b2 = p;
                ++n32; break;
            case 1:
                if (dict_order) { if (n1 == 0) step = p; else b3 = p; }
                else            { if (n1 == 0) b3   = p; else step = p; }
                ++n1; break;
            default: break;
        }
    }

    float* out_img = (float*)d_out;                 // y_img (output 0)
    float* out_up;                                  // y_img_update (output 1)
    if (out_size >= 2 * BB * SS) {
        out_up = (float*)d_out + BB * SS;
    } else {
        // harness only allocated output 0 — keep update in scratch
        cudaGetSymbolAddress((void**)&out_up, g_up);
    }

    k_hfilt<<<1, 512>>>();
    k_maskimg<<<(BB * SS) / 256, 256>>>(y_prev);
    k_radon<<<dim3(NA, BB), 512>>>(x_sino, angles);
    k_filter<<<dim3(NA, BB), 256>>>();
    k_backproj<<<dim3(SZ, BB), 256>>>(y_prev, angles, step, out_up);
    k_conv1<<<(BB * SS) / 256, 256>>>(out_up, y_cat, w1, b1);
    k_conv2<<<dim3(8, 32, BB), 256>>>(w2, b2);
    k_conv3<<<(BB * SS) / 256, 256>>>(w3, b3, out_img);
}

// round 4
// speedup vs baseline: 3.4452x; 3.4452x over previous
#include <cuda_runtime.h>
#include <math.h>

#define BB 4
#define NA 50
#define SZ 256
#define SS (SZ*SZ)
#define NC 32
#define PP 512
#define CEN 127.5f

// ---------------- scratch (static device allocations) ----------------
__device__ float g_h[PP];                // ramp filter impulse response
__device__ float g_imgm[BB*SS];          // masked y_img_prev
__device__ float g_diff[BB*NA*SZ];       // Ay - x
__device__ float g_filt[BB*NA*SZ];       // filtered sinogram (scaled)
__device__ float g_h1[BB*NC*SS];         // conv1 output
__device__ float g_h2[BB*NC*SS];         // conv2 output
__device__ float g_up[BB*SS];            // fallback y_img_update buffer

// ---------------- 1. ramp filter: exact closed form ----------------
// h = irfft(2*rfftfreq(P)):  h[0]=0.5, h[even!=0]=0, h[odd n] = -2/(P^2 sin^2(pi n/P))
__global__ void k_hfilt() {
    int n = threadIdx.x;  // 0..511
    float v;
    if (n == 0) {
        v = 0.5f;
    } else if ((n & 1) == 0) {
        v = 0.0f;
    } else {
        double s = sin(M_PI * (double)n / (double)PP);
        v = (float)(-2.0 / ((double)PP * (double)PP * s * s));
    }
    g_h[n] = v;
}

// ---------------- 2. mask input image ----------------
__global__ void k_maskimg(const float* __restrict__ yprev) {
    int idx = blockIdx.x * 256 + threadIdx.x;   // B*SS threads
    int p = idx & (SS - 1);
    int i = p >> 8, j = p & 255;
    float dy = (float)i - CEN, dx = (float)j - CEN;
    float m = (dy*dy + dx*dx <= 16384.0f) ? 1.0f : 0.0f;
    g_imgm[idx] = yprev[idx] * m;
}

// ---------------- bilinear sample, mode='constant' cval=0 ----------------
__device__ __forceinline__ float bilin256(const float* __restrict__ im, float r, float c) {
    float rf = floorf(r), cf = floorf(c);
    int r0 = (int)rf, c0 = (int)cf;
    float wr = r - rf, wc = c - cf;
    float v = 0.0f;
    bool r0v = (r0 >= 0) && (r0 <= 255);
    bool r1v = (r0 >= -1) && (r0 <= 254);
    bool c0v = (c0 >= 0) && (c0 <= 255);
    bool c1v = (c0 >= -1) && (c0 <= 254);
    if (r0v) {
        const float* row = im + r0 * SZ;
        if (c0v) v += row[c0]     * (1.0f - wr) * (1.0f - wc);
        if (c1v) v += row[c0 + 1] * (1.0f - wr) * wc;
    }
    if (r1v) {
        const float* row = im + (r0 + 1) * SZ;
        if (c0v) v += row[c0]     * wr * (1.0f - wc);
        if (c1v) v += row[c0 + 1] * wr * wc;
    }
    return v;
}

// ---------------- 3. radon forward + subtract x_sinogram ----------------
// grid (NA, BB), 1024 threads: s = tid&255, t-quarter = tid>>8 (64 samples each)
__global__ void __launch_bounds__(1024) k_radon(const float* __restrict__ x_sino,
                                                const float* __restrict__ angles) {
    __shared__ float s_red[1024];
    int a = blockIdx.x, b = blockIdx.y;
    int tid = threadIdx.x;
    int s = tid & 255, quart = tid >> 8;
    float ca, sa;
    __sincosf(angles[a], &sa, &ca);
    float sf = (float)s - CEN;
    const float* im = &g_imgm[b * SS];
    float sum = 0.0f;
    int t0 = quart * 64;
    #pragma unroll 4
    for (int t = t0; t < t0 + 64; ++t) {
        float tf = (float)t - CEN;
        float row = sf * sa + tf * ca + CEN;   // y + c
        float col = sf * ca - tf * sa + CEN;   // x + c
        sum += bilin256(im, row, col);
    }
    s_red[tid] = sum;
    __syncthreads();
    if (quart == 0) {
        float tot = s_red[s] + s_red[s + 256] + s_red[s + 512] + s_red[s + 768];
        int o = (b * NA + a) * SZ + s;
        g_diff[o] = tot - x_sino[o];
    }
}

// ---------------- 4. ramp filter: sparse circular convolution ----------------
// h is nonzero only at index 0 and odd indices -> 129 taps instead of 256.
__global__ void k_filter() {
    __shared__ float sd[SZ];
    __shared__ float sh[PP];
    int a = blockIdx.x, b = blockIdx.y;
    int n = threadIdx.x;
    int base = (b * NA + a) * SZ;
    sd[n] = g_diff[base + n];
    sh[n] = g_h[n];
    sh[n + 256] = g_h[n + 256];
    __syncthreads();
    float acc = 0.5f * sd[n];          // center tap h[0]=0.5 exact
    int m0 = (n & 1) ^ 1;              // opposite parity -> odd (n-m)
    #pragma unroll 8
    for (int j = 0; j < 128; ++j) {
        int m = m0 + 2 * j;
        acc += sd[m] * sh[(n - m + PP) & (PP - 1)];
    }
    g_filt[base + n] = acc * (float)(M_PI / (2.0 * NA));
}

// ---------------- 5. backprojection + update ----------------
__global__ void k_backproj(const float* __restrict__ yprev,
                           const float* __restrict__ angles,
                           const float* __restrict__ step,
                           float* __restrict__ out_up) {
    __shared__ float s_sino[25 * SZ];
    __shared__ float s_cos[NA], s_sin[NA];
    int i = blockIdx.x, b = blockIdx.y;
    int j = threadIdx.x;
    if (j < NA) { s_cos[j] = cosf(angles[j]); s_sin[j] = sinf(angles[j]); }
    __syncthreads();
    float xx = (float)j - CEN, yy = (float)i - CEN;
    float acc = 0.0f;
    for (int ch = 0; ch < 2; ++ch) {
        for (int al = 0; al < 25; ++al) {
            s_sino[al * SZ + j] = g_filt[(b * NA + ch * 25 + al) * SZ + j];
        }
        __syncthreads();
        #pragma unroll 5
        for (int al = 0; al < 25; ++al) {
            int a = ch * 25 + al;
            float det = xx * s_cos[a] + yy * s_sin[a] + CEN;
            float df = floorf(det);
            int i0 = (int)df;
            i0 = i0 < 0 ? 0 : (i0 > SZ - 2 ? SZ - 2 : i0);
            float w = det - (float)i0;
            float v = s_sino[al * SZ + i0] * (1.0f - w) + s_sino[al * SZ + i0 + 1] * w;
            if (det >= 0.0f && det <= (float)(SZ - 1)) acc += v;
        }
        __syncthreads();
    }
    float m = (xx*xx + yy*yy <= 16384.0f) ? 1.0f : 0.0f;
    int o = b * SS + i * SZ + j;
    out_up[o] = yprev[o] + step[0] * (acc * m);
}

// ---------------- 6. conv1: 2 -> 32, 3x3 SAME, ReLU ----------------
__global__ void k_conv1(const float* __restrict__ yup,
                        const float* __restrict__ ycat,
                        const float* __restrict__ w1,
                        const float* __restrict__ b1) {
    __shared__ float s_w[NC * 2 * 9];
    __shared__ float s_b[NC];
    int tid = threadIdx.x;
    for (int k = tid; k < NC * 18; k += 256) s_w[k] = w1[k];
    if (tid < NC) s_b[tid] = b1[tid];
    __syncthreads();
    int idx = blockIdx.x * 256 + tid;
    int b = idx >> 16;
    int p = idx & (SS - 1);
    int i = p >> 8, j = p & 255;
    float iv0[9], iv1[9];
    #pragma unroll
    for (int ky = 0; ky < 3; ++ky) {
        #pragma unroll
        for (int kx = 0; kx < 3; ++kx) {
            int y = i + ky - 1, x = j + kx - 1;
            bool ok = (y >= 0) && (y < SZ) && (x >= 0) && (x < SZ);
            int gi = b * SS + y * SZ + x;
            iv0[ky*3+kx] = ok ? yup[gi]  : 0.0f;
            iv1[ky*3+kx] = ok ? ycat[gi] : 0.0f;
        }
    }
    for (int oc = 0; oc < NC; ++oc) {
        float acc = s_b[oc];
        const float* w = &s_w[oc * 18];
        #pragma unroll
        for (int k = 0; k < 9; ++k) acc += iv0[k] * w[k];
        #pragma unroll
        for (int k = 0; k < 9; ++k) acc += iv1[k] * w[9 + k];
        g_h1[((b * NC + oc) << 16) + p] = fmaxf(acc, 0.0f);
    }
}

// ---------------- 7. conv2: 32 -> 32, 3x3 SAME, ReLU ----------------
#define ICH 16
__global__ void __launch_bounds__(256) k_conv2(const float* __restrict__ w2,
                                               const float* __restrict__ b2) {
    __shared__ __align__(16) float s_w[ICH * 9 * 32];   // [ic][k][oc]
    __shared__ float s_in[ICH * 10 * 34];               // [ic][row][col]
    __shared__ float s_b[NC];
    int tid = threadIdx.x;
    int q = tid & 7, r = (tid >> 3) & 7, og = tid >> 6;
    int b = blockIdx.z;
    int gx0 = blockIdx.x * 32 - 1;
    int gy0 = blockIdx.y * 8 - 1;
    if (tid < NC) s_b[tid] = b2[tid];

    float acc[8][4];
    #pragma unroll
    for (int o = 0; o < 8; ++o)
        #pragma unroll
        for (int p = 0; p < 4; ++p) acc[o][p] = 0.0f;

    for (int cc = 0; cc < 2; ++cc) {
        int icb = cc * ICH;
        __syncthreads();
        for (int idx = tid; idx < ICH * 288; idx += 256) {
            int ic = idx / 288, rem = idx % 288;
            int k = rem >> 5, oc = rem & 31;
            s_w[idx] = w2[oc * 288 + (icb + ic) * 9 + k];
        }
        for (int idx = tid; idx < ICH * 340; idx += 256) {
            int ic = idx / 340, rem = idx % 340;
            int rr = rem / 34, ccx = rem % 34;
            int gy = gy0 + rr, gx = gx0 + ccx;
            bool ok = (gy >= 0) && (gy < SZ) && (gx >= 0) && (gx < SZ);
            s_in[idx] = ok ? g_h1[((b * NC + icb + ic) << 16) + gy * SZ + gx] : 0.0f;
        }
        __syncthreads();

        for (int ic = 0; ic < ICH; ++ic) {
            const float* inb = &s_in[ic * 340];
            const float* wb  = &s_w[ic * 288];
            #pragma unroll
            for (int ky = 0; ky < 3; ++ky) {
                float iv[6];
                const float* rowp = inb + (r + ky) * 34 + q * 4;
                #pragma unroll
                for (int m = 0; m < 6; ++m) iv[m] = rowp[m];
                #pragma unroll
                for (int kx = 0; kx < 3; ++kx) {
                    const float4 wa = *(const float4*)&wb[(ky * 3 + kx) * 32 + og * 8];
                    const float4 wbv = *(const float4*)&wb[(ky * 3 + kx) * 32 + og * 8 + 4];
                    float wv[8] = {wa.x, wa.y, wa.z, wa.w, wbv.x, wbv.y, wbv.z, wbv.w};
                    #pragma unroll
                    for (int o = 0; o < 8; ++o)
                        #pragma unroll
                        for (int p = 0; p < 4; ++p)
                            acc[o][p] += wv[o] * iv[kx + p];
                }
            }
        }
    }
    int gy = blockIdx.y * 8 + r;
    int gxb = blockIdx.x * 32 + q * 4;
    #pragma unroll
    for (int o = 0; o < 8; ++o) {
        int oc = og * 8 + o;
        float bias = s_b[oc];
        int base = ((b * NC + oc) << 16) + gy * SZ + gxb;
        #pragma unroll
        for (int p = 0; p < 4; ++p)
            g_h2[base + p] = fmaxf(acc[o][p] + bias, 0.0f);
    }
}

// ---------------- 8. conv3: 32 -> 1, 3x3 SAME ----------------
__global__ void k_conv3(const float* __restrict__ w3,
                        const float* __restrict__ b3,
                        float* __restrict__ out_img) {
    __shared__ float s_w[NC * 9];
    int tid = threadIdx.x;
    for (int k = tid; k < NC * 9; k += 256) s_w[k] = w3[k];
    __syncthreads();
    int idx = blockIdx.x * 256 + tid;
    int b = idx >> 16;
    int p = idx & (SS - 1);
    int i = p >> 8, j = p & 255;
    float acc = b3[0];
    for (int ic = 0; ic < NC; ++ic) {
        const float* in = &g_h2[(b * NC + ic) << 16];
        const float* w = &s_w[ic * 9];
        #pragma unroll
        for (int ky = 0; ky < 3; ++ky) {
            int y = i + ky - 1;
            if (y < 0 || y >= SZ) continue;
            #pragma unroll
            for (int kx = 0; kx < 3; ++kx) {
                int x = j + kx - 1;
                if (x < 0 || x >= SZ) continue;
                acc += in[y * SZ + x] * w[ky * 3 + kx];
            }
        }
    }
    out_img[idx] = acc;
}

// ---------------- launch: input-order-robust dispatch ----------------
extern "C" void kernel_launch(void* const* d_in, const int* in_sizes, int n_in,
                              void* d_out, int out_size) {
    const float *x_sino = 0, *y_prev = 0, *y_cat = 0, *angles = 0, *step = 0;
    const float *w1 = 0, *b1 = 0, *w2 = 0, *b2 = 0, *w3 = 0, *b3 = 0;

    int ix = -1;
    for (int i = 0; i < n_in; ++i) if (in_sizes[i] == 51200) ix = i;
    bool dict_order = (ix == 0);

    int n262 = 0, n32 = 0, n1 = 0;
    for (int i = 0; i < n_in; ++i) {
        const float* p = (const float*)d_in[i];
        switch (in_sizes[i]) {
            case 51200: x_sino = p; break;
            case 50:    angles = p; break;
            case 576:   w1 = p; break;
            case 9216:  w2 = p; break;
            case 288:   w3 = p; break;
            case 262144:
                if (dict_order) { if (n262 == 0) y_prev = p; else y_cat = p; }
                else            { if (n262 == 0) y_cat  = p; else y_prev = p; }
                ++n262; break;
            case 32:
                if (n32 == 0) b1 = p; else b2 = p;
                ++n32; break;
            case 1:
                if (dict_order) { if (n1 == 0) step = p; else b3 = p; }
                else            { if (n1 == 0) b3   = p; else step = p; }
                ++n1; break;
            default: break;
        }
    }

    float* out_img = (float*)d_out;                 // y_img (output 0)
    float* out_up;                                  // y_img_update (output 1)
    if (out_size >= 2 * BB * SS) {
        out_up = (float*)d_out + BB * SS;
    } else {
        cudaGetSymbolAddress((void**)&out_up, g_up);
    }

    k_hfilt<<<1, 512>>>();
    k_maskimg<<<(BB * SS) / 256, 256>>>(y_prev);
    k_radon<<<dim3(NA, BB), 1024>>>(x_sino, angles);
    k_filter<<<dim3(NA, BB), 256>>>();
    k_backproj<<<dim3(SZ, BB), 256>>>(y_prev, angles, step, out_up);
    k_conv1<<<(BB * SS) / 256, 256>>>(out_up, y_cat, w1, b1);
    k_conv2<<<dim3(8, 32, BB), 256>>>(w2, b2);
    k_conv3<<<(BB * SS) / 256, 256>>>(w3, b3, out_img);
}

// round 5
// speedup vs baseline: 3.6110x; 1.0481x over previous
#include <cuda_runtime.h>
#include <math.h>

#define BB 4
#define NA 50
#define SZ 256
#define SS (SZ*SZ)
#define NC 32
#define PP 512
#define CEN 127.5f

typedef unsigned long long u64;

// ---- packed f32x2 helpers (sm_103a dual-rate fp32 path) ----
__device__ __forceinline__ u64 pk2(float lo, float hi) {
    u64 r; asm("mov.b64 %0, {%1, %2};" : "=l"(r) : "f"(lo), "f"(hi)); return r;
}
__device__ __forceinline__ u64 fma2(u64 a, u64 b, u64 c) {
    u64 d; asm("fma.rn.f32x2 %0, %1, %2, %3;" : "=l"(d) : "l"(a), "l"(b), "l"(c)); return d;
}
__device__ __forceinline__ void unpk2(u64 v, float& lo, float& hi) {
    asm("mov.b64 {%0, %1}, %2;" : "=f"(lo), "=f"(hi) : "l"(v));
}

// ---------------- scratch (static device allocations) ----------------
__device__ float g_h[PP];                // ramp filter impulse response
__device__ float g_imgm[BB*SS];          // masked y_img_prev
__device__ float g_diff[BB*NA*SZ];       // Ay - x
__device__ float g_filt[BB*NA*SZ];       // filtered sinogram (scaled)
__device__ float g_h1[BB*NC*SS];         // conv1 output
__device__ float g_h2[BB*NC*SS];         // conv2 output
__device__ float g_up[BB*SS];            // fallback y_img_update buffer

// ---------------- 1. ramp filter: exact closed form ----------------
__global__ void k_hfilt() {
    int n = threadIdx.x;  // 0..511
    float v;
    if (n == 0) {
        v = 0.5f;
    } else if ((n & 1) == 0) {
        v = 0.0f;
    } else {
        double s = sin(M_PI * (double)n / (double)PP);
        v = (float)(-2.0 / ((double)PP * (double)PP * s * s));
    }
    g_h[n] = v;
}

// ---------------- 2. mask input image ----------------
__global__ void k_maskimg(const float* __restrict__ yprev) {
    int idx = blockIdx.x * 256 + threadIdx.x;
    int p = idx & (SS - 1);
    int i = p >> 8, j = p & 255;
    float dy = (float)i - CEN, dx = (float)j - CEN;
    float m = (dy*dy + dx*dx <= 16384.0f) ? 1.0f : 0.0f;
    g_imgm[idx] = yprev[idx] * m;
}

// ---------------- branchless bilinear, mode='constant' cval=0 ----------------
__device__ __forceinline__ float bilin256(const float* __restrict__ im, float r, float c) {
    float rf = floorf(r), cf = floorf(c);
    int r0 = (int)rf, c0 = (int)cf;
    float wr = r - rf, wc = c - cf;
    int r0c = min(max(r0, 0), 255), r1c = min(max(r0 + 1, 0), 255);
    int c0c = min(max(c0, 0), 255), c1c = min(max(c0 + 1, 0), 255);
    float mr0 = (r0 == r0c) ? 1.0f : 0.0f;
    float mr1 = (r0 + 1 == r1c) ? 1.0f : 0.0f;
    float mc0 = (c0 == c0c) ? 1.0f : 0.0f;
    float mc1 = (c0 + 1 == c1c) ? 1.0f : 0.0f;
    float v00 = im[r0c * SZ + c0c] * mr0 * mc0;
    float v01 = im[r0c * SZ + c1c] * mr0 * mc1;
    float v10 = im[r1c * SZ + c0c] * mr1 * mc0;
    float v11 = im[r1c * SZ + c1c] * mr1 * mc1;
    float top = v00 + (v01 - v00) * wc;
    float bot = v10 + (v11 - v10) * wc;
    return top + (bot - top) * wr;
}

// ---------------- 3. radon forward + subtract x_sinogram ----------------
__global__ void __launch_bounds__(1024) k_radon(const float* __restrict__ x_sino,
                                                const float* __restrict__ angles) {
    __shared__ float s_red[1024];
    int a = blockIdx.x, b = blockIdx.y;
    int tid = threadIdx.x;
    int s = tid & 255, quart = tid >> 8;
    float ca, sa;
    __sincosf(angles[a], &sa, &ca);
    float sf = (float)s - CEN;
    const float* im = &g_imgm[b * SS];
    float sum = 0.0f;
    int t0 = quart * 64;
    #pragma unroll 4
    for (int t = t0; t < t0 + 64; ++t) {
        float tf = (float)t - CEN;
        float row = sf * sa + tf * ca + CEN;
        float col = sf * ca - tf * sa + CEN;
        sum += bilin256(im, row, col);
    }
    s_red[tid] = sum;
    __syncthreads();
    if (quart == 0) {
        float tot = s_red[s] + s_red[s + 256] + s_red[s + 512] + s_red[s + 768];
        int o = (b * NA + a) * SZ + s;
        g_diff[o] = tot - x_sino[o];
    }
}

// ---------------- 4. ramp filter: sparse circular convolution ----------------
__global__ void k_filter() {
    __shared__ float sd[SZ];
    __shared__ float sh[PP];
    int a = blockIdx.x, b = blockIdx.y;
    int n = threadIdx.x;
    int base = (b * NA + a) * SZ;
    sd[n] = g_diff[base + n];
    sh[n] = g_h[n];
    sh[n + 256] = g_h[n + 256];
    __syncthreads();
    float acc = 0.5f * sd[n];
    int m0 = (n & 1) ^ 1;
    #pragma unroll 8
    for (int j = 0; j < 128; ++j) {
        int m = m0 + 2 * j;
        acc += sd[m] * sh[(n - m + PP) & (PP - 1)];
    }
    g_filt[base + n] = acc * (float)(M_PI / (2.0 * NA));
}

// ---------------- 5. backprojection + update ----------------
__global__ void k_backproj(const float* __restrict__ yprev,
                           const float* __restrict__ angles,
                           const float* __restrict__ step,
                           float* __restrict__ out_up) {
    __shared__ float s_sino[25 * SZ];
    __shared__ float s_cos[NA], s_sin[NA];
    int i = blockIdx.x, b = blockIdx.y;
    int j = threadIdx.x;
    if (j < NA) { s_cos[j] = cosf(angles[j]); s_sin[j] = sinf(angles[j]); }
    __syncthreads();
    float xx = (float)j - CEN, yy = (float)i - CEN;
    float acc = 0.0f;
    for (int ch = 0; ch < 2; ++ch) {
        for (int al = 0; al < 25; ++al) {
            s_sino[al * SZ + j] = g_filt[(b * NA + ch * 25 + al) * SZ + j];
        }
        __syncthreads();
        #pragma unroll 5
        for (int al = 0; al < 25; ++al) {
            int a = ch * 25 + al;
            float det = xx * s_cos[a] + yy * s_sin[a] + CEN;
            float df = floorf(det);
            int i0 = (int)df;
            i0 = i0 < 0 ? 0 : (i0 > SZ - 2 ? SZ - 2 : i0);
            float w = det - (float)i0;
            float v = s_sino[al * SZ + i0] * (1.0f - w) + s_sino[al * SZ + i0 + 1] * w;
            if (det >= 0.0f && det <= (float)(SZ - 1)) acc += v;
        }
        __syncthreads();
    }
    float m = (xx*xx + yy*yy <= 16384.0f) ? 1.0f : 0.0f;
    int o = b * SS + i * SZ + j;
    out_up[o] = yprev[o] + step[0] * (acc * m);
}

// ---------------- 6. conv1: 2 -> 32, 3x3 SAME, ReLU (f32x2 over oc-pairs) ----
__global__ void k_conv1(const float* __restrict__ yup,
                        const float* __restrict__ ycat,
                        const float* __restrict__ w1,
                        const float* __restrict__ b1) {
    // s_w2[k][oc]: k = ic*9 + ky*3 + kx (0..17), oc consecutive -> LDS.128 pairs
    __shared__ __align__(16) float s_w2[18 * 32];
    __shared__ __align__(8)  float s_b[NC];
    int tid = threadIdx.x;
    for (int idx = tid; idx < 18 * 32; idx += 256) {
        int kk = idx >> 5, oc = idx & 31;
        s_w2[idx] = w1[oc * 18 + kk];
    }
    if (tid < NC) s_b[tid] = b1[tid];
    __syncthreads();
    int idx = blockIdx.x * 256 + tid;
    int b = idx >> 16;
    int p = idx & (SS - 1);
    int i = p >> 8, j = p & 255;
    float iv[18];
    #pragma unroll
    for (int ky = 0; ky < 3; ++ky) {
        #pragma unroll
        for (int kx = 0; kx < 3; ++kx) {
            int y = i + ky - 1, x = j + kx - 1;
            bool ok = (y >= 0) && (y < SZ) && (x >= 0) && (x < SZ);
            int gi = b * SS + y * SZ + x;
            iv[ky*3+kx]     = ok ? yup[gi]  : 0.0f;
            iv[9 + ky*3+kx] = ok ? ycat[gi] : 0.0f;
        }
    }
    u64 acc2[16];
    #pragma unroll
    for (int op = 0; op < 16; ++op) acc2[op] = ((const u64*)s_b)[op];  // packed biases
    #pragma unroll
    for (int k = 0; k < 18; ++k) {
        u64 ib = pk2(iv[k], iv[k]);
        const ulonglong2* wrow = (const ulonglong2*)&s_w2[k * 32];
        #pragma unroll
        for (int g = 0; g < 8; ++g) {
            ulonglong2 wv = wrow[g];
            acc2[2*g]   = fma2(wv.x, ib, acc2[2*g]);
            acc2[2*g+1] = fma2(wv.y, ib, acc2[2*g+1]);
        }
    }
    #pragma unroll
    for (int op = 0; op < 16; ++op) {
        float lo, hi; unpk2(acc2[op], lo, hi);
        g_h1[((b * NC + 2*op)     << 16) + p] = fmaxf(lo, 0.0f);
        g_h1[((b * NC + 2*op + 1) << 16) + p] = fmaxf(hi, 0.0f);
    }
}

// ---------------- 7. conv2: 32 -> 32, 3x3 SAME, ReLU (f32x2 over oc-pairs) ----
#define ICH 16
__global__ void __launch_bounds__(256) k_conv2(const float* __restrict__ w2,
                                               const float* __restrict__ b2) {
    __shared__ __align__(16) float s_w[ICH * 9 * 32];   // [ic][k][oc]
    __shared__ float s_in[ICH * 10 * 34];               // [ic][row][col]
    __shared__ float s_b[NC];
    int tid = threadIdx.x;
    int q = tid & 7, r = (tid >> 3) & 7, og = tid >> 6;
    int b = blockIdx.z;
    int gx0 = blockIdx.x * 32 - 1;
    int gy0 = blockIdx.y * 8 - 1;
    if (tid < NC) s_b[tid] = b2[tid];

    u64 acc2[4][4];   // [oc-pair within og][px]
    #pragma unroll
    for (int op = 0; op < 4; ++op)
        #pragma unroll
        for (int p = 0; p < 4; ++p) acc2[op][p] = 0ULL;

    for (int cc = 0; cc < 2; ++cc) {
        int icb = cc * ICH;
        __syncthreads();
        for (int idx = tid; idx < ICH * 288; idx += 256) {
            int ic = idx / 288, rem = idx % 288;
            int k = rem >> 5, oc = rem & 31;
            s_w[idx] = w2[oc * 288 + (icb + ic) * 9 + k];
        }
        for (int idx = tid; idx < ICH * 340; idx += 256) {
            int ic = idx / 340, rem = idx % 340;
            int rr = rem / 34, ccx = rem % 34;
            int gy = gy0 + rr, gx = gx0 + ccx;
            bool ok = (gy >= 0) && (gy < SZ) && (gx >= 0) && (gx < SZ);
            s_in[idx] = ok ? g_h1[((b * NC + icb + ic) << 16) + gy * SZ + gx] : 0.0f;
        }
        __syncthreads();

        for (int ic = 0; ic < ICH; ++ic) {
            const float* inb = &s_in[ic * 340];
            const float* wb  = &s_w[ic * 288];
            #pragma unroll
            for (int ky = 0; ky < 3; ++ky) {
                const float* rowp = inb + (r + ky) * 34 + q * 4;
                u64 ivp[6];
                #pragma unroll
                for (int m = 0; m < 6; ++m) { float v = rowp[m]; ivp[m] = pk2(v, v); }
                #pragma unroll
                for (int kx = 0; kx < 3; ++kx) {
                    const ulonglong2 wv0 = *(const ulonglong2*)&wb[(ky*3+kx)*32 + og*8];
                    const ulonglong2 wv1 = *(const ulonglong2*)&wb[(ky*3+kx)*32 + og*8 + 4];
                    u64 wp[4] = {wv0.x, wv0.y, wv1.x, wv1.y};
                    #pragma unroll
                    for (int op = 0; op < 4; ++op)
                        #pragma unroll
                        for (int p = 0; p < 4; ++p)
                            acc2[op][p] = fma2(wp[op], ivp[kx + p], acc2[op][p]);
                }
            }
        }
    }
    int gy = blockIdx.y * 8 + r;
    int gxb = blockIdx.x * 32 + q * 4;
    #pragma unroll
    for (int op = 0; op < 4; ++op) {
        int oc0 = og * 8 + 2 * op;
        float blo = s_b[oc0], bhi = s_b[oc0 + 1];
        float4 vlo, vhi;
        float l0,h0,l1,h1,l2,h2,l3,h3;
        unpk2(acc2[op][0], l0, h0); unpk2(acc2[op][1], l1, h1);
        unpk2(acc2[op][2], l2, h2); unpk2(acc2[op][3], l3, h3);
        vlo.x = fmaxf(l0 + blo, 0.0f); vlo.y = fmaxf(l1 + blo, 0.0f);
        vlo.z = fmaxf(l2 + blo, 0.0f); vlo.w = fmaxf(l3 + blo, 0.0f);
        vhi.x = fmaxf(h0 + bhi, 0.0f); vhi.y = fmaxf(h1 + bhi, 0.0f);
        vhi.z = fmaxf(h2 + bhi, 0.0f); vhi.w = fmaxf(h3 + bhi, 0.0f);
        *(float4*)&g_h2[((b * NC + oc0)     << 16) + gy * SZ + gxb] = vlo;
        *(float4*)&g_h2[((b * NC + oc0 + 1) << 16) + gy * SZ + gxb] = vhi;
    }
}

// ---------------- 8. conv3: 32 -> 1, 3x3 SAME ----------------
__global__ void k_conv3(const float* __restrict__ w3,
                        const float* __restrict__ b3,
                        float* __restrict__ out_img) {
    __shared__ float s_w[NC * 9];
    int tid = threadIdx.x;
    for (int k = tid; k < NC * 9; k += 256) s_w[k] = w3[k];
    __syncthreads();
    int idx = blockIdx.x * 256 + tid;
    int b = idx >> 16;
    int p = idx & (SS - 1);
    int i = p >> 8, j = p & 255;
    float acc = b3[0];
    for (int ic = 0; ic < NC; ++ic) {
        const float* in = &g_h2[(b * NC + ic) << 16];
        const float* w = &s_w[ic * 9];
        #pragma unroll
        for (int ky = 0; ky < 3; ++ky) {
            int y = i + ky - 1;
            if (y < 0 || y >= SZ) continue;
            #pragma unroll
            for (int kx = 0; kx < 3; ++kx) {
                int x = j + kx - 1;
                if (x < 0 || x >= SZ) continue;
                acc += in[y * SZ + x] * w[ky * 3 + kx];
            }
        }
    }
    out_img[idx] = acc;
}

// ---------------- launch: input-order-robust dispatch ----------------
extern "C" void kernel_launch(void* const* d_in, const int* in_sizes, int n_in,
                              void* d_out, int out_size) {
    const float *x_sino = 0, *y_prev = 0, *y_cat = 0, *angles = 0, *step = 0;
    const float *w1 = 0, *b1 = 0, *w2 = 0, *b2 = 0, *w3 = 0, *b3 = 0;

    int ix = -1;
    for (int i = 0; i < n_in; ++i) if (in_sizes[i] == 51200) ix = i;
    bool dict_order = (ix == 0);

    int n262 = 0, n32 = 0, n1 = 0;
    for (int i = 0; i < n_in; ++i) {
        const float* p = (const float*)d_in[i];
        switch (in_sizes[i]) {
            case 51200: x_sino = p; break;
            case 50:    angles = p; break;
            case 576:   w1 = p; break;
            case 9216:  w2 = p; break;
            case 288:   w3 = p; break;
            case 262144:
                if (dict_order) { if (n262 == 0) y_prev = p; else y_cat = p; }
                else            { if (n262 == 0) y_cat  = p; else y_prev = p; }
                ++n262; break;
            case 32:
                if (n32 == 0) b1 = p; else b2 = p;
                ++n32; break;
            case 1:
                if (dict_order) { if (n1 == 0) step = p; else b3 = p; }
                else            { if (n1 == 0) b3   = p; else step = p; }
                ++n1; break;
            default: break;
        }
    }

    float* out_img = (float*)d_out;
    float* out_up;
    if (out_size >= 2 * BB * SS) {
        out_up = (float*)d_out + BB * SS;
    } else {
        cudaGetSymbolAddress((void**)&out_up, g_up);
    }

    k_hfilt<<<1, 512>>>();
    k_maskimg<<<(BB * SS) / 256, 256>>>(y_prev);
    k_radon<<<dim3(NA, BB), 1024>>>(x_sino, angles);
    k_filter<<<dim3(NA, BB), 256>>>();
    k_backproj<<<dim3(SZ, BB), 256>>>(y_prev, angles, step, out_up);
    k_conv1<<<(BB * SS) / 256, 256>>>(out_up, y_cat, w1, b1);
    k_conv2<<<dim3(8, 32, BB), 256>>>(w2, b2);
    k_conv3<<<(BB * SS) / 256, 256>>>(w3, b3, out_img);
}

// round 6
// speedup vs baseline: 5.4067x; 1.4973x over previous
#include <cuda_runtime.h>
#include <math.h>

#define BB 4
#define NA 50
#define SZ 256
#define SS (SZ*SZ)
#define NC 32
#define PP 512
#define CEN 127.5f
#define NZ 8                       // radon band splits

typedef unsigned long long u64;

// ---- packed f32x2 helpers (sm_103a dual-rate fp32 path) ----
__device__ __forceinline__ u64 pk2(float lo, float hi) {
    u64 r; asm("mov.b64 %0, {%1, %2};" : "=l"(r) : "f"(lo), "f"(hi)); return r;
}
__device__ __forceinline__ u64 fma2(u64 a, u64 b, u64 c) {
    u64 d; asm("fma.rn.f32x2 %0, %1, %2, %3;" : "=l"(d) : "l"(a), "l"(b), "l"(c)); return d;
}
__device__ __forceinline__ void unpk2(u64 v, float& lo, float& hi) {
    asm("mov.b64 {%0, %1}, %2;" : "=f"(lo), "=f"(hi) : "l"(v));
}

// ---------------- scratch (static device allocations) ----------------
__device__ float g_h[PP];                // ramp filter impulse response
__device__ float g_imgm[BB*SS];          // masked y_img_prev
__device__ float g_part[NZ*BB*NA*SZ];    // radon partial sums per band
__device__ float g_filt[BB*NA*SZ];       // filtered sinogram (scaled)
__device__ float g_h1[BB*NC*SS];         // conv1 output
__device__ float g_h2[BB*NC*SS];         // conv2 output
__device__ float g_up[BB*SS];            // fallback y_img_update buffer

// ---------------- 1. ramp filter: exact closed form ----------------
__global__ void k_hfilt() {
    int n = threadIdx.x;  // 0..511
    float v;
    if (n == 0) {
        v = 0.5f;
    } else if ((n & 1) == 0) {
        v = 0.0f;
    } else {
        double s = sin(M_PI * (double)n / (double)PP);
        v = (float)(-2.0 / ((double)PP * (double)PP * s * s));
    }
    g_h[n] = v;
}

// ---------------- 2. mask input image ----------------
__global__ void k_maskimg(const float* __restrict__ yprev) {
    int idx = blockIdx.x * 256 + threadIdx.x;
    int p = idx & (SS - 1);
    int i = p >> 8, j = p & 255;
    float dy = (float)i - CEN, dx = (float)j - CEN;
    float m = (dy*dy + dx*dx <= 16384.0f) ? 1.0f : 0.0f;
    g_imgm[idx] = yprev[idx] * m;
}

// ---------------- 3. radon forward: band-tiled via shared memory ----------
// grid (NA, BB, NZ), 256 threads = detector bin s.
// Band z owns samples with r0 = floor(row) in [lo, hi): lo = 32z (z>0, else -1),
// hi = 32z+32. smem holds image rows [32z .. 32z+32] (halo; row 256 zero).
__global__ void __launch_bounds__(256) k_radon(const float* __restrict__ angles) {
    __shared__ float s_band[33][257];
    int a = blockIdx.x, b = blockIdx.y, z = blockIdx.z;
    int s = threadIdx.x;
    int y0 = z * 32;
    int lo = (z == 0) ? -1 : y0;
    int hi = y0 + 32;

    // cooperative band load (coalesced; row 256 zero-padded)
    const float* im = &g_imgm[b * SS];
    #pragma unroll
    for (int i = 0; i < 33; ++i) {
        int gy = y0 + i;
        s_band[i][s] = (gy <= 255) ? im[gy * SZ + s] : 0.0f;
    }
    __syncthreads();

    float ca, sa;
    __sincosf(angles[a], &sa, &ca);
    float sf = (float)s - CEN;
    // row(t) = rowA + t*ca ; col(t) = colA - t*sa
    float rowA = sf * sa - CEN * ca + CEN;
    float colA = sf * ca + CEN * sa + CEN;

    // conservative t-interval whose floor(row) could fall in [lo, hi)
    float tmin, tmax;
    if (fabsf(ca) > 1e-6f) {
        float t1 = ((float)lo - 0.5f - rowA) / ca;
        float t2 = ((float)hi + 0.5f - rowA) / ca;
        tmin = fminf(t1, t2) - 1.0f;
        tmax = fmaxf(t1, t2) + 1.0f;
    } else {
        bool inb = (rowA >= (float)lo - 1.0f) && (rowA < (float)hi + 1.0f);
        tmin = inb ? 0.0f : 1.0f;
        tmax = inb ? 255.0f : 0.0f;
    }
    int ts = max(0, (int)floorf(tmin));
    int te = min(255, (int)ceilf(tmax));

    float sum = 0.0f;
    for (int t = ts; t <= te; ++t) {
        float row = rowA + (float)t * ca;
        float rf = floorf(row);
        int r0 = (int)rf;
        if (r0 < lo || r0 >= hi) continue;        // exact ownership test
        float wr = row - rf;
        float col = colA - (float)t * sa;
        float cf = floorf(col);
        int c0 = (int)cf;
        float wc = col - cf;
        int c0c = min(max(c0, 0), 255);
        int c1c = min(max(c0 + 1, 0), 255);
        float mc0 = (c0 == c0c) ? 1.0f : 0.0f;
        float mc1 = (c0 + 1 == c1c) ? 1.0f : 0.0f;
        float mr0 = (r0 >= 0) ? 1.0f : 0.0f;      // r0 == -1 edge
        int lr = r0 - y0;
        int lrc = max(lr, 0);
        float v00 = s_band[lrc][c0c],     v01 = s_band[lrc][c1c];
        float v10 = s_band[lr + 1][c0c],  v11 = s_band[lr + 1][c1c];  // row 256 halo = 0
        float top = mc0 * (1.0f - wc) * v00 + mc1 * wc * v01;
        float bot = mc0 * (1.0f - wc) * v10 + mc1 * wc * v11;
        sum += mr0 * (1.0f - wr) * top + wr * bot;
    }
    g_part[((z * BB + b) * NA + a) * SZ + s] = sum;
}

// ---------------- 4. ramp filter: fold partials + subtract + sparse conv ----
__global__ void k_filter(const float* __restrict__ x_sino) {
    __shared__ float sd[SZ];
    __shared__ float sh[PP];
    int a = blockIdx.x, b = blockIdx.y;
    int n = threadIdx.x;
    int base = (b * NA + a) * SZ + n;
    float d = -x_sino[base];
    #pragma unroll
    for (int z = 0; z < NZ; ++z) d += g_part[((z * BB + b) * NA + a) * SZ + n];
    sd[n] = d;
    sh[n] = g_h[n];
    sh[n + 256] = g_h[n + 256];
    __syncthreads();
    float acc = 0.5f * sd[n];
    int m0 = (n & 1) ^ 1;
    #pragma unroll 8
    for (int j = 0; j < 128; ++j) {
        int m = m0 + 2 * j;
        acc += sd[m] * sh[(n - m + PP) & (PP - 1)];
    }
    g_filt[base] = acc * (float)(M_PI / (2.0 * NA));
}

// ---------------- 5. backprojection + update ----------------
__global__ void k_backproj(const float* __restrict__ yprev,
                           const float* __restrict__ angles,
                           const float* __restrict__ step,
                           float* __restrict__ out_up) {
    __shared__ float s_sino[25 * SZ];
    __shared__ float s_cos[NA], s_sin[NA];
    int i = blockIdx.x, b = blockIdx.y;
    int j = threadIdx.x;
    if (j < NA) { s_cos[j] = cosf(angles[j]); s_sin[j] = sinf(angles[j]); }
    __syncthreads();
    float xx = (float)j - CEN, yy = (float)i - CEN;
    float acc = 0.0f;
    for (int ch = 0; ch < 2; ++ch) {
        for (int al = 0; al < 25; ++al) {
            s_sino[al * SZ + j] = g_filt[(b * NA + ch * 25 + al) * SZ + j];
        }
        __syncthreads();
        #pragma unroll 5
        for (int al = 0; al < 25; ++al) {
            int a = ch * 25 + al;
            float det = xx * s_cos[a] + yy * s_sin[a] + CEN;
            float df = floorf(det);
            int i0 = (int)df;
            i0 = i0 < 0 ? 0 : (i0 > SZ - 2 ? SZ - 2 : i0);
            float w = det - (float)i0;
            float v = s_sino[al * SZ + i0] * (1.0f - w) + s_sino[al * SZ + i0 + 1] * w;
            if (det >= 0.0f && det <= (float)(SZ - 1)) acc += v;
        }
        __syncthreads();
    }
    float m = (xx*xx + yy*yy <= 16384.0f) ? 1.0f : 0.0f;
    int o = b * SS + i * SZ + j;
    out_up[o] = yprev[o] + step[0] * (acc * m);
}

// ---------------- 6. conv1: 2 -> 32, 3x3 SAME, ReLU (f32x2 over oc-pairs) ----
__global__ void k_conv1(const float* __restrict__ yup,
                        const float* __restrict__ ycat,
                        const float* __restrict__ w1,
                        const float* __restrict__ b1) {
    __shared__ __align__(16) float s_w2[18 * 32];
    __shared__ __align__(8)  float s_b[NC];
    int tid = threadIdx.x;
    for (int idx = tid; idx < 18 * 32; idx += 256) {
        int kk = idx >> 5, oc = idx & 31;
        s_w2[idx] = w1[oc * 18 + kk];
    }
    if (tid < NC) s_b[tid] = b1[tid];
    __syncthreads();
    int idx = blockIdx.x * 256 + tid;
    int b = idx >> 16;
    int p = idx & (SS - 1);
    int i = p >> 8, j = p & 255;
    float iv[18];
    #pragma unroll
    for (int ky = 0; ky < 3; ++ky) {
        #pragma unroll
        for (int kx = 0; kx < 3; ++kx) {
            int y = i + ky - 1, x = j + kx - 1;
            bool ok = (y >= 0) && (y < SZ) && (x >= 0) && (x < SZ);
            int gi = b * SS + y * SZ + x;
            iv[ky*3+kx]     = ok ? yup[gi]  : 0.0f;
            iv[9 + ky*3+kx] = ok ? ycat[gi] : 0.0f;
        }
    }
    u64 acc2[16];
    #pragma unroll
    for (int op = 0; op < 16; ++op) acc2[op] = ((const u64*)s_b)[op];
    #pragma unroll
    for (int k = 0; k < 18; ++k) {
        u64 ib = pk2(iv[k], iv[k]);
        const ulonglong2* wrow = (const ulonglong2*)&s_w2[k * 32];
        #pragma unroll
        for (int g = 0; g < 8; ++g) {
            ulonglong2 wv = wrow[g];
            acc2[2*g]   = fma2(wv.x, ib, acc2[2*g]);
            acc2[2*g+1] = fma2(wv.y, ib, acc2[2*g+1]);
        }
    }
    #pragma unroll
    for (int op = 0; op < 16; ++op) {
        float lo, hi; unpk2(acc2[op], lo, hi);
        g_h1[((b * NC + 2*op)     << 16) + p] = fmaxf(lo, 0.0f);
        g_h1[((b * NC + 2*op + 1) << 16) + p] = fmaxf(hi, 0.0f);
    }
}

// ---------------- 7. conv2: 32 -> 32, 3x3 SAME, ReLU (f32x2, padded tile) ----
#define ICH 16
#define RW 36   // padded row width (16B-aligned vector loads)
__global__ void __launch_bounds__(256) k_conv2(const float* __restrict__ w2,
                                               const float* __restrict__ b2) {
    __shared__ __align__(16) float s_w[ICH * 9 * 32];   // [ic][k][oc]
    __shared__ __align__(16) float s_in[ICH * 10 * RW]; // [ic][row][col], padded
    __shared__ float s_b[NC];
    int tid = threadIdx.x;
    int q = tid & 7, r = (tid >> 3) & 7, og = tid >> 6;
    int b = blockIdx.z;
    int gx0 = blockIdx.x * 32 - 1;
    int gy0 = blockIdx.y * 8 - 1;
    if (tid < NC) s_b[tid] = b2[tid];

    u64 acc2[4][4];
    #pragma unroll
    for (int op = 0; op < 4; ++op)
        #pragma unroll
        for (int p = 0; p < 4; ++p) acc2[op][p] = 0ULL;

    for (int cc = 0; cc < 2; ++cc) {
        int icb = cc * ICH;
        __syncthreads();
        for (int idx = tid; idx < ICH * 288; idx += 256) {
            int ic = idx / 288, rem = idx % 288;
            int k = rem >> 5, oc = rem & 31;
            s_w[idx] = w2[oc * 288 + (icb + ic) * 9 + k];
        }
        for (int idx = tid; idx < ICH * 10 * RW; idx += 256) {
            int ic = idx / (10 * RW), rem = idx % (10 * RW);
            int rr = rem / RW, ccx = rem % RW;
            int gy = gy0 + rr, gx = gx0 + ccx;
            bool ok = (ccx < 34) && (gy >= 0) && (gy < SZ) && (gx >= 0) && (gx < SZ);
            s_in[idx] = ok ? g_h1[((b * NC + icb + ic) << 16) + gy * SZ + gx] : 0.0f;
        }
        __syncthreads();

        for (int ic = 0; ic < ICH; ++ic) {
            const float* inb = &s_in[ic * 10 * RW];
            const float* wb  = &s_w[ic * 288];
            #pragma unroll
            for (int ky = 0; ky < 3; ++ky) {
                const float* rowp = inb + (r + ky) * RW + q * 4;
                float4 va = *(const float4*)rowp;
                float2 vb = *(const float2*)(rowp + 4);
                float ivf[6] = {va.x, va.y, va.z, va.w, vb.x, vb.y};
                u64 ivp[6];
                #pragma unroll
                for (int m = 0; m < 6; ++m) ivp[m] = pk2(ivf[m], ivf[m]);
                #pragma unroll
                for (int kx = 0; kx < 3; ++kx) {
                    const ulonglong2 wv0 = *(const ulonglong2*)&wb[(ky*3+kx)*32 + og*8];
                    const ulonglong2 wv1 = *(const ulonglong2*)&wb[(ky*3+kx)*32 + og*8 + 4];
                    u64 wp[4] = {wv0.x, wv0.y, wv1.x, wv1.y};
                    #pragma unroll
                    for (int op = 0; op < 4; ++op)
                        #pragma unroll
                        for (int p = 0; p < 4; ++p)
                            acc2[op][p] = fma2(wp[op], ivp[kx + p], acc2[op][p]);
                }
            }
        }
    }
    int gy = blockIdx.y * 8 + r;
    int gxb = blockIdx.x * 32 + q * 4;
    #pragma unroll
    for (int op = 0; op < 4; ++op) {
        int oc0 = og * 8 + 2 * op;
        float blo = s_b[oc0], bhi = s_b[oc0 + 1];
        float4 vlo, vhi;
        float l0,h0,l1,h1,l2,h2,l3,h3;
        unpk2(acc2[op][0], l0, h0); unpk2(acc2[op][1], l1, h1);
        unpk2(acc2[op][2], l2, h2); unpk2(acc2[op][3], l3, h3);
        vlo.x = fmaxf(l0 + blo, 0.0f); vlo.y = fmaxf(l1 + blo, 0.0f);
        vlo.z = fmaxf(l2 + blo, 0.0f); vlo.w = fmaxf(l3 + blo, 0.0f);
        vhi.x = fmaxf(h0 + bhi, 0.0f); vhi.y = fmaxf(h1 + bhi, 0.0f);
        vhi.z = fmaxf(h2 + bhi, 0.0f); vhi.w = fmaxf(h3 + bhi, 0.0f);
        *(float4*)&g_h2[((b * NC + oc0)     << 16) + gy * SZ + gxb] = vlo;
        *(float4*)&g_h2[((b * NC + oc0 + 1) << 16) + gy * SZ + gxb] = vhi;
    }
}

// ---------------- 8. conv3: 32 -> 1, 3x3 SAME ----------------
__global__ void k_conv3(const float* __restrict__ w3,
                        const float* __restrict__ b3,
                        float* __restrict__ out_img) {
    __shared__ float s_w[NC * 9];
    int tid = threadIdx.x;
    for (int k = tid; k < NC * 9; k += 256) s_w[k] = w3[k];
    __syncthreads();
    int idx = blockIdx.x * 256 + tid;
    int b = idx >> 16;
    int p = idx & (SS - 1);
    int i = p >> 8, j = p & 255;
    float acc = b3[0];
    for (int ic = 0; ic < NC; ++ic) {
        const float* in = &g_h2[(b * NC + ic) << 16];
        const float* w = &s_w[ic * 9];
        #pragma unroll
        for (int ky = 0; ky < 3; ++ky) {
            int y = i + ky - 1;
            if (y < 0 || y >= SZ) continue;
            #pragma unroll
            for (int kx = 0; kx < 3; ++kx) {
                int x = j + kx - 1;
                if (x < 0 || x >= SZ) continue;
                acc += in[y * SZ + x] * w[ky * 3 + kx];
            }
        }
    }
    out_img[idx] = acc;
}

// ---------------- launch: input-order-robust dispatch ----------------
extern "C" void kernel_launch(void* const* d_in, const int* in_sizes, int n_in,
                              void* d_out, int out_size) {
    const float *x_sino = 0, *y_prev = 0, *y_cat = 0, *angles = 0, *step = 0;
    const float *w1 = 0, *b1 = 0, *w2 = 0, *b2 = 0, *w3 = 0, *b3 = 0;

    int ix = -1;
    for (int i = 0; i < n_in; ++i) if (in_sizes[i] == 51200) ix = i;
    bool dict_order = (ix == 0);

    int n262 = 0, n32 = 0, n1 = 0;
    for (int i = 0; i < n_in; ++i) {
        const float* p = (const float*)d_in[i];
        switch (in_sizes[i]) {
            case 51200: x_sino = p; break;
            case 50:    angles = p; break;
            case 576:   w1 = p; break;
            case 9216:  w2 = p; break;
            case 288:   w3 = p; break;
            case 262144:
                if (dict_order) { if (n262 == 0) y_prev = p; else y_cat = p; }
                else            { if (n262 == 0) y_cat  = p; else y_prev = p; }
                ++n262; break;
            case 32:
                if (n32 == 0) b1 = p; else b2 = p;
                ++n32; break;
            case 1:
                if (dict_order) { if (n1 == 0) step = p; else b3 = p; }
                else            { if (n1 == 0) b3   = p; else step = p; }
                ++n1; break;
            default: break;
        }
    }

    float* out_img = (float*)d_out;
    float* out_up;
    if (out_size >= 2 * BB * SS) {
        out_up = (float*)d_out + BB * SS;
    } else {
        cudaGetSymbolAddress((void**)&out_up, g_up);
    }

    k_hfilt<<<1, 512>>>();
    k_maskimg<<<(BB * SS) / 256, 256>>>(y_prev);
    k_radon<<<dim3(NA, BB, NZ), 256>>>(angles);
    k_filter<<<dim3(NA, BB), 256>>>(x_sino);
    k_backproj<<<dim3(SZ, BB), 256>>>(y_prev, angles, step, out_up);
    k_conv1<<<(BB * SS) / 256, 256>>>(out_up, y_cat, w1, b1);
    k_conv2<<<dim3(8, 32, BB), 256>>>(w2, b2);
    k_conv3<<<(BB * SS) / 256, 256>>>(w3, b3, out_img);
}